// round 1
// baseline (speedup 1.0000x reference)
#include <cuda_runtime.h>

// ---------------------------------------------------------------------------
// Problem constants
// ---------------------------------------------------------------------------
#define BSZ  32
#define CC   1536
#define CI   768
#define HH   14
#define WW   14
#define HJ   28
#define WJ   28
#define NN   784          // HJ*WJ (query positions)
#define MM   196          // pooled positions (NN/4)
#define CTPG 2304         // stacked theta|phi|g output channels

// ---------------------------------------------------------------------------
// Scratch (device globals — no allocations allowed)
// ---------------------------------------------------------------------------
__device__ float g_xj  [(size_t)BSZ * CC   * NN];   // joint input (also residual)
__device__ float g_tpg [(size_t)BSZ * CTPG * NN];   // stacked conv outputs
__device__ float g_phi [(size_t)BSZ * CI   * MM];   // pooled phi
__device__ float g_gp  [(size_t)BSZ * CI   * MM];   // pooled g
__device__ float g_attn[(size_t)BSZ * NN   * MM];   // f / attn (in-place softmax)
__device__ float g_y   [(size_t)BSZ * CI   * NN];   // attention output
__device__ float g_wstk[(size_t)CTPG * CC];         // stacked weights
__device__ float g_bstk[CTPG];                      // stacked biases
__device__ float g_escale[CC];                      // BN folded scale
__device__ float g_eshift[CC];                      // BN folded shift (incl. b_W)

// ---------------------------------------------------------------------------
// joint: (B*4, C, 14, 14) -> (B, C, 28, 28) as 2x2 grid of views
// ---------------------------------------------------------------------------
__global__ void joint_kernel(const float* __restrict__ x) {
    long idx = (long)blockIdx.x * blockDim.x + threadIdx.x;
    const long total = (long)BSZ * CC * NN;
    if (idx >= total) return;
    int n = (int)(idx % NN);
    int c = (int)((idx / NN) % CC);
    int b = (int)(idx / ((long)NN * CC));
    int hj = n / WJ, wj = n % WJ;
    int v = ((hj >= HH) ? 2 : 0) + ((wj >= WW) ? 1 : 0);
    int hl = (hj >= HH) ? hj - HH : hj;
    int wl = (wj >= WW) ? wj - WW : wj;
    g_xj[idx] = x[(((long)(b * 4 + v) * CC + c) * HH + hl) * WW + wl];
}

// ---------------------------------------------------------------------------
// stack theta/phi/g weights + biases
// ---------------------------------------------------------------------------
__global__ void stack_kernel(const float* __restrict__ wt, const float* __restrict__ wp,
                             const float* __restrict__ wg, const float* __restrict__ bt,
                             const float* __restrict__ bp, const float* __restrict__ bg) {
    long idx = (long)blockIdx.x * blockDim.x + threadIdx.x;
    if (idx < (long)CTPG * CC) {
        int r = (int)(idx / CC);
        int c = (int)(idx % CC);
        const float* src = (r < CI) ? wt : ((r < 2 * CI) ? wp : wg);
        int rr = (r < CI) ? r : ((r < 2 * CI) ? r - CI : r - 2 * CI);
        g_wstk[idx] = src[(long)rr * CC + c];
    }
    if (idx < CTPG) {
        int r = (int)idx;
        g_bstk[r] = (r < CI) ? bt[r] : ((r < 2 * CI) ? bp[r - CI] : bg[r - 2 * CI]);
    }
}

// ---------------------------------------------------------------------------
// BN folding: out = acc*escale + eshift + resid
//   v = acc + b_W;  bn(v) = v*s + (beta - mean*s) with s = gamma*rsqrt(var+eps)
// ---------------------------------------------------------------------------
__global__ void bnprep_kernel(const float* __restrict__ gamma, const float* __restrict__ beta,
                              const float* __restrict__ mean, const float* __restrict__ var,
                              const float* __restrict__ bW) {
    int m = blockIdx.x * blockDim.x + threadIdx.x;
    if (m < CC) {
        float s = gamma[m] * rsqrtf(var[m] + 1e-5f);
        g_escale[m] = s;
        g_eshift[m] = beta[m] - mean[m] * s + bW[m] * s;
    }
}

// ---------------------------------------------------------------------------
// 2x2 maxpool on phi/g parts of g_tpg -> g_phi / g_gp
// ---------------------------------------------------------------------------
__global__ void pool_kernel() {
    int idx = blockIdx.x * blockDim.x + threadIdx.x;
    const int total = BSZ * CI * MM;
    if (idx >= 2 * total) return;
    int which = (idx >= total) ? 1 : 0;       // 0: phi, 1: g
    int r = which ? idx - total : idx;
    int m = r % MM;
    int c = (r / MM) % CI;
    int b = r / (MM * CI);
    int hm = m / 14, wm = m % 14;
    const float* src = g_tpg + ((long)b * CTPG + (which ? 2 * CI : CI) + c) * NN;
    int base = (2 * hm) * WJ + 2 * wm;
    float v = fmaxf(fmaxf(src[base], src[base + 1]),
                    fmaxf(src[base + WJ], src[base + WJ + 1]));
    (which ? g_gp : g_phi)[r] = v;
}

// ---------------------------------------------------------------------------
// Row softmax over MM=196 (one warp per row, in place on g_attn)
// ---------------------------------------------------------------------------
__global__ void softmax_kernel() {
    int warp = (blockIdx.x * blockDim.x + threadIdx.x) >> 5;
    int lane = threadIdx.x & 31;
    const int rows = BSZ * NN;
    if (warp >= rows) return;
    float* row = g_attn + (long)warp * MM;
    float vals[7];
    float mx = -1e30f;
#pragma unroll
    for (int s = 0; s < 7; s++) {
        int i = lane + s * 32;
        vals[s] = (i < MM) ? row[i] : -1e30f;
        mx = fmaxf(mx, vals[s]);
    }
#pragma unroll
    for (int o = 16; o; o >>= 1) mx = fmaxf(mx, __shfl_xor_sync(0xffffffffu, mx, o));
    float sum = 0.f;
#pragma unroll
    for (int s = 0; s < 7; s++) {
        int i = lane + s * 32;
        vals[s] = (i < MM) ? __expf(vals[s] - mx) : 0.f;
        sum += vals[s];
    }
#pragma unroll
    for (int o = 16; o; o >>= 1) sum += __shfl_xor_sync(0xffffffffu, sum, o);
    float inv = 1.f / sum;
#pragma unroll
    for (int s = 0; s < 7; s++) {
        int i = lane + s * 32;
        if (i < MM) row[i] = vals[s] * inv;
    }
}

// ---------------------------------------------------------------------------
// Generic batched SGEMM: C[b] = A[b] (MxK) * B[b] (KxN)  (+ epilogue)
//   AT: A stored as (K x M) row-major (i.e., A[m,k] = Ap[k*M + m])
//   BT: B stored as (N x K) row-major (i.e., B[k,n] = Bp[n*K + k])
//   EPI 0: plain store; 1: +bias[m]; 2: BN-fold + residual (writes final out)
// 64x64x16 tiling, 256 threads, 4x4 per-thread, float4 smem reads.
// ---------------------------------------------------------------------------
template <bool AT, bool BT, int EPI>
__global__ void __launch_bounds__(256)
gemm_kernel(const float* __restrict__ A, const float* __restrict__ B,
            float* __restrict__ Cp, int M, int Nn, int K,
            long sA, long sB, long sC,
            const float* __restrict__ bias,
            const float* __restrict__ resid, long sR) {
    constexpr int BM = 64, BN = 64, BK = 16, PAD = 4;
    __shared__ float As[BK][BM + PAD];
    __shared__ float Bs[BK][BN + PAD];

    int b = blockIdx.z;
    const float* Ab = A + (long)b * sA;
    const float* Bb = B + (long)b * sB;
    float* Cb = Cp + (long)b * sC;
    int m0 = blockIdx.y * BM;
    int n0 = blockIdx.x * BN;
    int tid = threadIdx.x;
    int tx = tid & 15, ty = tid >> 4;

    float acc[4][4] = {};

    for (int k0 = 0; k0 < K; k0 += BK) {
        // ---- load A tile into As[k][m]
        if (!AT) {
            int i = tid >> 4;   // m part
            int j = tid & 15;   // k part
#pragma unroll
            for (int s = 0; s < 4; s++) {
                int m = m0 + i + s * 16;
                int k = k0 + j;
                As[j][i + s * 16] = (m < M && k < K) ? Ab[(long)m * K + k] : 0.f;
            }
        } else {
            int j = tid >> 6;   // k part (0..3)
            int i = tid & 63;   // m part
#pragma unroll
            for (int s = 0; s < 4; s++) {
                int k = k0 + j + s * 4;
                int m = m0 + i;
                As[j + s * 4][i] = (m < M && k < K) ? Ab[(long)k * M + m] : 0.f;
            }
        }
        // ---- load B tile into Bs[k][n]
        if (!BT) {
            int j = tid >> 6;   // k part
            int n = tid & 63;
#pragma unroll
            for (int s = 0; s < 4; s++) {
                int k = k0 + j + s * 4;
                int nn = n0 + n;
                Bs[j + s * 4][n] = (k < K && nn < Nn) ? Bb[(long)k * Nn + nn] : 0.f;
            }
        } else {
            int n = tid >> 4;   // n part
            int j = tid & 15;   // k part
#pragma unroll
            for (int s = 0; s < 4; s++) {
                int nn = n0 + n + s * 16;
                int k = k0 + j;
                Bs[j][n + s * 16] = (k < K && nn < Nn) ? Bb[(long)nn * K + k] : 0.f;
            }
        }
        __syncthreads();

#pragma unroll
        for (int k = 0; k < BK; k++) {
            float4 a4 = *(const float4*)&As[k][ty * 4];
            float4 b4 = *(const float4*)&Bs[k][tx * 4];
            float a[4] = {a4.x, a4.y, a4.z, a4.w};
            float bb[4] = {b4.x, b4.y, b4.z, b4.w};
#pragma unroll
            for (int i = 0; i < 4; i++)
#pragma unroll
                for (int j = 0; j < 4; j++) acc[i][j] = fmaf(a[i], bb[j], acc[i][j]);
        }
        __syncthreads();
    }

#pragma unroll
    for (int i = 0; i < 4; i++) {
        int m = m0 + ty * 4 + i;
        if (m >= M) continue;
#pragma unroll
        for (int j = 0; j < 4; j++) {
            int n = n0 + tx * 4 + j;
            if (n >= Nn) continue;
            float v = acc[i][j];
            if (EPI == 1) v += bias[m];
            if (EPI == 2)
                v = v * g_escale[m] + g_eshift[m] + resid[(long)b * sR + (long)m * Nn + n];
            Cb[(long)m * Nn + n] = v;
        }
    }
}

// ---------------------------------------------------------------------------
// Launch
// ---------------------------------------------------------------------------
extern "C" void kernel_launch(void* const* d_in, const int* in_sizes, int n_in,
                              void* d_out, int out_size) {
    const float* x     = (const float*)d_in[0];
    const float* wt    = (const float*)d_in[1];
    const float* bt    = (const float*)d_in[2];
    const float* wp    = (const float*)d_in[3];
    const float* bp    = (const float*)d_in[4];
    const float* wg    = (const float*)d_in[5];
    const float* bg    = (const float*)d_in[6];
    const float* wW    = (const float*)d_in[7];
    const float* bW    = (const float*)d_in[8];
    const float* gamma = (const float*)d_in[9];
    const float* beta  = (const float*)d_in[10];
    const float* mean  = (const float*)d_in[11];
    const float* var   = (const float*)d_in[12];
    float* out = (float*)d_out;

    float *p_xj, *p_tpg, *p_phi, *p_gp, *p_attn, *p_y, *p_wstk, *p_bstk;
    cudaGetSymbolAddress((void**)&p_xj, g_xj);
    cudaGetSymbolAddress((void**)&p_tpg, g_tpg);
    cudaGetSymbolAddress((void**)&p_phi, g_phi);
    cudaGetSymbolAddress((void**)&p_gp, g_gp);
    cudaGetSymbolAddress((void**)&p_attn, g_attn);
    cudaGetSymbolAddress((void**)&p_y, g_y);
    cudaGetSymbolAddress((void**)&p_wstk, g_wstk);
    cudaGetSymbolAddress((void**)&p_bstk, g_bstk);

    // 1. joint gather
    {
        long total = (long)BSZ * CC * NN;
        joint_kernel<<<(unsigned)((total + 255) / 256), 256>>>(x);
    }
    // 2. weight stack + BN prep
    {
        long total = (long)CTPG * CC;
        stack_kernel<<<(unsigned)((total + 255) / 256), 256>>>(wt, wp, wg, bt, bp, bg);
        bnprep_kernel<<<(CC + 255) / 256, 256>>>(gamma, beta, mean, var, bW);
    }
    // 3. stacked theta|phi|g conv: tpg[b] = Wstk (2304x1536) * xj[b] (1536x784)
    {
        dim3 grid((NN + 63) / 64, (CTPG + 63) / 64, BSZ);
        gemm_kernel<false, false, 1><<<grid, 256>>>(
            p_wstk, p_xj, p_tpg, CTPG, NN, CC,
            0L, (long)CC * NN, (long)CTPG * NN, p_bstk, nullptr, 0L);
    }
    // 4. 2x2 maxpool on phi/g
    {
        int total = 2 * BSZ * CI * MM;
        pool_kernel<<<(total + 255) / 256, 256>>>();
    }
    // 5. f[b] (784x196) = theta[b]^T (784x768) * phi[b] (768x196)
    {
        dim3 grid((MM + 63) / 64, (NN + 63) / 64, BSZ);
        gemm_kernel<true, false, 0><<<grid, 256>>>(
            p_tpg, p_phi, p_attn, NN, MM, CI,
            (long)CTPG * NN, (long)CI * MM, (long)NN * MM, nullptr, nullptr, 0L);
    }
    // 6. softmax rows (in place)
    {
        int rows = BSZ * NN;                 // one warp per row
        softmax_kernel<<<(rows * 32 + 255) / 256, 256>>>();
    }
    // 7. y[b] (768x784) = g[b] (768x196) * attn[b]^T (196x784)
    {
        dim3 grid((NN + 63) / 64, (CI + 63) / 64, BSZ);
        gemm_kernel<false, true, 0><<<grid, 256>>>(
            p_gp, p_attn, p_y, CI, NN, MM,
            (long)CI * MM, (long)NN * MM, (long)CI * NN, nullptr, nullptr, 0L);
    }
    // 8. out[b] = BN(w_W (1536x768) * y[b] (768x784) + b_W) + xj[b]
    {
        dim3 grid((NN + 63) / 64, (CC + 63) / 64, BSZ);
        gemm_kernel<false, false, 2><<<grid, 256>>>(
            wW, p_y, out, CC, NN, CI,
            0L, (long)CI * NN, (long)CC * NN, nullptr, p_xj, (long)CC * NN);
    }
}

// round 3
// speedup vs baseline: 2.0628x; 2.0628x over previous
#include <cuda_runtime.h>
#include <cuda_bf16.h>
#include <cstdint>

// ---------------------------------------------------------------------------
// Problem constants
// ---------------------------------------------------------------------------
#define BSZ  32
#define CC   1536
#define CI   768
#define HH   14
#define WW   14
#define HJ   28
#define WJ   28
#define NN   784
#define MM   196
#define CTPG 2304

// ---------------------------------------------------------------------------
// Scratch (device globals)
// ---------------------------------------------------------------------------
__device__ float g_xj  [(size_t)BSZ * CC * NN];            // fp32 joint (residual)
__device__ __nv_bfloat16 g_xhT[(size_t)BSZ * NN * CC];     // xj^T hi
__device__ __nv_bfloat16 g_xlT[(size_t)BSZ * NN * CC];     // xj^T lo
__device__ float g_tpg [(size_t)BSZ * CTPG * NN];
__device__ float g_phi [(size_t)BSZ * CI * MM];
__device__ float g_gp  [(size_t)BSZ * CI * MM];
__device__ float g_attn[(size_t)BSZ * NN * MM];
__device__ float g_y   [(size_t)BSZ * CI * NN];
__device__ __nv_bfloat16 g_yhT[(size_t)BSZ * NN * CI];
__device__ __nv_bfloat16 g_ylT[(size_t)BSZ * NN * CI];
__device__ __nv_bfloat16 g_whi[(size_t)CTPG * CC];
__device__ __nv_bfloat16 g_wlo[(size_t)CTPG * CC];
__device__ __nv_bfloat16 g_wWhi[(size_t)CC * CI];
__device__ __nv_bfloat16 g_wWlo[(size_t)CC * CI];
__device__ float g_bstk[CTPG];
__device__ float g_escale[CC];
__device__ float g_eshift[CC];

// ---------------------------------------------------------------------------
// PTX helpers (all base-ISA, no 'a'-features)
// ---------------------------------------------------------------------------
__device__ __forceinline__ uint32_t smem_u32(const void* p) {
    uint32_t a;
    asm("{ .reg .u64 t; cvta.to.shared.u64 t, %1; cvt.u32.u64 %0, t; }" : "=r"(a) : "l"(p));
    return a;
}
__device__ __forceinline__ void ldm_x4(uint32_t* r, uint32_t addr) {
    asm volatile("ldmatrix.sync.aligned.m8n8.x4.shared.b16 {%0,%1,%2,%3}, [%4];"
                 : "=r"(r[0]), "=r"(r[1]), "=r"(r[2]), "=r"(r[3]) : "r"(addr));
}
__device__ __forceinline__ void mma16816(float* d, const uint32_t* a, uint32_t b0, uint32_t b1) {
    asm volatile("mma.sync.aligned.m16n8k16.row.col.f32.bf16.bf16.f32 "
                 "{%0,%1,%2,%3}, {%4,%5,%6,%7}, {%8,%9}, {%0,%1,%2,%3};"
                 : "+f"(d[0]), "+f"(d[1]), "+f"(d[2]), "+f"(d[3])
                 : "r"(a[0]), "r"(a[1]), "r"(a[2]), "r"(a[3]), "r"(b0), "r"(b1));
}
__device__ __forceinline__ void cpa16(uint32_t dst, const void* src, int srcsz) {
    asm volatile("cp.async.cg.shared.global [%0], [%1], 16, %2;"
                 :: "r"(dst), "l"(src), "r"(srcsz));
}
#define CPA_COMMIT()  asm volatile("cp.async.commit_group;" ::: "memory")
#define CPA_WAIT(n)   asm volatile("cp.async.wait_group %0;" :: "n"(n) : "memory")

// ---------------------------------------------------------------------------
// joint: (B*4, C, 14, 14) -> (B, C, 28, 28)
// ---------------------------------------------------------------------------
__global__ void joint_kernel(const float* __restrict__ x) {
    long idx = (long)blockIdx.x * blockDim.x + threadIdx.x;
    const long total = (long)BSZ * CC * NN;
    if (idx >= total) return;
    int n = (int)(idx % NN);
    int c = (int)((idx / NN) % CC);
    int b = (int)(idx / ((long)NN * CC));
    int hj = n / WJ, wj = n % WJ;
    int v = ((hj >= HH) ? 2 : 0) + ((wj >= WW) ? 1 : 0);
    int hl = (hj >= HH) ? hj - HH : hj;
    int wl = (wj >= WW) ? wj - WW : wj;
    g_xj[idx] = x[(((long)(b * 4 + v) * CC + c) * HH + hl) * WW + wl];
}

// ---------------------------------------------------------------------------
// tiled transpose + bf16 hi/lo split: in [b][R][Cn] fp32 -> out [b][Cn][R]
// ---------------------------------------------------------------------------
__global__ void tsplit_kernel(const float* __restrict__ in,
                              __nv_bfloat16* __restrict__ hi,
                              __nv_bfloat16* __restrict__ lo, int R, int Cn) {
    __shared__ float t[32][33];
    int b = blockIdx.z;
    int r0 = blockIdx.y * 32, c0 = blockIdx.x * 32;
    const float* ib = in + (long)b * R * Cn;
    int tx = threadIdx.x, ty = threadIdx.y;
#pragma unroll
    for (int s = 0; s < 32; s += 8) {
        int r = r0 + ty + s, c = c0 + tx;
        t[ty + s][tx] = (r < R && c < Cn) ? ib[(long)r * Cn + c] : 0.f;
    }
    __syncthreads();
    long ob = (long)b * Cn * R;
#pragma unroll
    for (int s = 0; s < 32; s += 8) {
        int c = c0 + ty + s, r = r0 + tx;
        if (c < Cn && r < R) {
            float v = t[tx][ty + s];
            __nv_bfloat16 h = __float2bfloat16(v);
            hi[ob + (long)c * R + r] = h;
            lo[ob + (long)c * R + r] = __float2bfloat16(v - __bfloat162float(h));
        }
    }
}

// ---------------------------------------------------------------------------
// weight stacking + bf16 split
// ---------------------------------------------------------------------------
__global__ void wsplit_stack_kernel(const float* __restrict__ wt, const float* __restrict__ wp,
                                    const float* __restrict__ wg, const float* __restrict__ bt,
                                    const float* __restrict__ bp, const float* __restrict__ bg) {
    long idx = (long)blockIdx.x * blockDim.x + threadIdx.x;
    if (idx < (long)CTPG * CC) {
        int r = (int)(idx / CC), c = (int)(idx % CC);
        const float* src = (r < CI) ? wt : ((r < 2 * CI) ? wp : wg);
        int rr = (r < CI) ? r : ((r < 2 * CI) ? r - CI : r - 2 * CI);
        float v = src[(long)rr * CC + c];
        __nv_bfloat16 h = __float2bfloat16(v);
        g_whi[idx] = h;
        g_wlo[idx] = __float2bfloat16(v - __bfloat162float(h));
    }
    if (idx < CTPG) {
        int r = (int)idx;
        g_bstk[r] = (r < CI) ? bt[r] : ((r < 2 * CI) ? bp[r - CI] : bg[r - 2 * CI]);
    }
}

__global__ void wsplitW_kernel(const float* __restrict__ wW) {
    long idx = (long)blockIdx.x * blockDim.x + threadIdx.x;
    if (idx >= (long)CC * CI) return;
    float v = wW[idx];
    __nv_bfloat16 h = __float2bfloat16(v);
    g_wWhi[idx] = h;
    g_wWlo[idx] = __float2bfloat16(v - __bfloat162float(h));
}

__global__ void bnprep_kernel(const float* __restrict__ gamma, const float* __restrict__ beta,
                              const float* __restrict__ mean, const float* __restrict__ var,
                              const float* __restrict__ bW) {
    int m = blockIdx.x * blockDim.x + threadIdx.x;
    if (m < CC) {
        float s = gamma[m] * rsqrtf(var[m] + 1e-5f);
        g_escale[m] = s;
        g_eshift[m] = beta[m] - mean[m] * s + bW[m] * s;
    }
}

// ---------------------------------------------------------------------------
// 2x2 maxpool on phi/g parts of g_tpg
// ---------------------------------------------------------------------------
__global__ void pool_kernel() {
    int idx = blockIdx.x * blockDim.x + threadIdx.x;
    const int total = BSZ * CI * MM;
    if (idx >= 2 * total) return;
    int which = (idx >= total) ? 1 : 0;
    int r = which ? idx - total : idx;
    int m = r % MM;
    int c = (r / MM) % CI;
    int b = r / (MM * CI);
    int hm = m / 14, wm = m % 14;
    const float* src = g_tpg + ((long)b * CTPG + (which ? 2 * CI : CI) + c) * NN;
    int base = (2 * hm) * WJ + 2 * wm;
    float v = fmaxf(fmaxf(src[base], src[base + 1]),
                    fmaxf(src[base + WJ], src[base + WJ + 1]));
    (which ? g_gp : g_phi)[r] = v;
}

// ---------------------------------------------------------------------------
// row softmax over MM=196
// ---------------------------------------------------------------------------
__global__ void softmax_kernel() {
    int warp = (blockIdx.x * blockDim.x + threadIdx.x) >> 5;
    int lane = threadIdx.x & 31;
    if (warp >= BSZ * NN) return;
    float* row = g_attn + (long)warp * MM;
    float vals[7];
    float mx = -1e30f;
#pragma unroll
    for (int s = 0; s < 7; s++) {
        int i = lane + s * 32;
        vals[s] = (i < MM) ? row[i] : -1e30f;
        mx = fmaxf(mx, vals[s]);
    }
#pragma unroll
    for (int o = 16; o; o >>= 1) mx = fmaxf(mx, __shfl_xor_sync(0xffffffffu, mx, o));
    float sum = 0.f;
#pragma unroll
    for (int s = 0; s < 7; s++) {
        int i = lane + s * 32;
        vals[s] = (i < MM) ? __expf(vals[s] - mx) : 0.f;
        sum += vals[s];
    }
#pragma unroll
    for (int o = 16; o; o >>= 1) sum += __shfl_xor_sync(0xffffffffu, sum, o);
    float inv = 1.f / sum;
#pragma unroll
    for (int s = 0; s < 7; s++) {
        int i = lane + s * 32;
        if (i < MM) row[i] = vals[s] * inv;
    }
}

// ---------------------------------------------------------------------------
// SIMT fp32 GEMM (attention GEMMs only)
// ---------------------------------------------------------------------------
template <bool AT, bool BT>
__global__ void __launch_bounds__(256)
gemm_kernel(const float* __restrict__ A, const float* __restrict__ B,
            float* __restrict__ Cp, int M, int Nn, int K,
            long sA, long sB, long sC) {
    constexpr int BM = 64, BN = 64, BK = 16, PAD = 4;
    __shared__ float As[BK][BM + PAD];
    __shared__ float Bs[BK][BN + PAD];
    int b = blockIdx.z;
    const float* Ab = A + (long)b * sA;
    const float* Bb = B + (long)b * sB;
    float* Cb = Cp + (long)b * sC;
    int m0 = blockIdx.y * BM, n0 = blockIdx.x * BN;
    int tid = threadIdx.x;
    int tx = tid & 15, ty = tid >> 4;
    float acc[4][4] = {};
    for (int k0 = 0; k0 < K; k0 += BK) {
        if (!AT) {
            int i = tid >> 4, j = tid & 15;
#pragma unroll
            for (int s = 0; s < 4; s++) {
                int m = m0 + i + s * 16, k = k0 + j;
                As[j][i + s * 16] = (m < M && k < K) ? Ab[(long)m * K + k] : 0.f;
            }
        } else {
            int j = tid >> 6, i = tid & 63;
#pragma unroll
            for (int s = 0; s < 4; s++) {
                int k = k0 + j + s * 4, m = m0 + i;
                As[j + s * 4][i] = (m < M && k < K) ? Ab[(long)k * M + m] : 0.f;
            }
        }
        if (!BT) {
            int j = tid >> 6, n = tid & 63;
#pragma unroll
            for (int s = 0; s < 4; s++) {
                int k = k0 + j + s * 4, nn = n0 + n;
                Bs[j + s * 4][n] = (k < K && nn < Nn) ? Bb[(long)k * Nn + nn] : 0.f;
            }
        } else {
            int n = tid >> 4, j = tid & 15;
#pragma unroll
            for (int s = 0; s < 4; s++) {
                int nn = n0 + n + s * 16, k = k0 + j;
                Bs[j][n + s * 16] = (k < K && nn < Nn) ? Bb[(long)nn * K + k] : 0.f;
            }
        }
        __syncthreads();
#pragma unroll
        for (int k = 0; k < BK; k++) {
            float4 a4 = *(const float4*)&As[k][ty * 4];
            float4 b4 = *(const float4*)&Bs[k][tx * 4];
            float a[4] = {a4.x, a4.y, a4.z, a4.w};
            float bb[4] = {b4.x, b4.y, b4.z, b4.w};
#pragma unroll
            for (int i = 0; i < 4; i++)
#pragma unroll
                for (int j = 0; j < 4; j++) acc[i][j] = fmaf(a[i], bb[j], acc[i][j]);
        }
        __syncthreads();
    }
#pragma unroll
    for (int i = 0; i < 4; i++) {
        int m = m0 + ty * 4 + i;
        if (m >= M) continue;
#pragma unroll
        for (int j = 0; j < 4; j++) {
            int n = n0 + tx * 4 + j;
            if (n >= Nn) continue;
            Cb[(long)m * Nn + n] = acc[i][j];
        }
    }
}

// ---------------------------------------------------------------------------
// bf16-split tensor GEMM via mma.sync (m16n8k16), cp.async double buffering.
//   D[m][n] = sum_k A[m][k]*B[n][k] over 3 passes: (Ahi,Bhi),(Alo,Bhi),(Ahi,Blo)
//   CTA tile 128x128, BK=32. 8 warps = 2(M) x 4(N); warp tile 64x32.
//   EPI 1: +bstk[m]    EPI 2: *escale[m]+eshift[m]+resid
// A is [M][K] (M multiple of 128, K multiple of 32); B is [b][NN][K].
// ---------------------------------------------------------------------------
template <int EPI>
__global__ void __launch_bounds__(256, 2)
mma_gemm_kernel(const __nv_bfloat16* __restrict__ Ahi, const __nv_bfloat16* __restrict__ Alo,
                const __nv_bfloat16* __restrict__ Bhi, const __nv_bfloat16* __restrict__ Blo,
                float* __restrict__ Cp, int K, long sC,
                const float* __restrict__ resid) {
    __shared__ __nv_bfloat16 sA[2][128][40];   // 40-elem (80B) stride: conflict-free ldmatrix
    __shared__ __nv_bfloat16 sB[2][128][40];

    const int tid = threadIdx.x;
    const int lane = tid & 31;
    const int wid = tid >> 5;
    const int wm = wid & 1;          // warp M index (0..1) -> 64 rows
    const int wn = wid >> 1;         // warp N index (0..3) -> 32 cols
    const int m0 = blockIdx.y * 128;
    const int n0 = blockIdx.x * 128;
    const int b  = blockIdx.z;

    const int NK = K / 32;
    const int total = 3 * NK;
    const long aBase = (long)m0 * K;
    const long bBase = (long)b * NN * (long)K;
    const __nv_bfloat16* Asrc[3] = {Ahi + aBase, Alo + aBase, Ahi + aBase};
    const __nv_bfloat16* Bsrc[3] = {Bhi + bBase, Bhi + bBase, Blo + bBase};

    float acc[4][4][4];
#pragma unroll
    for (int i = 0; i < 4; i++)
#pragma unroll
        for (int j = 0; j < 4; j++)
#pragma unroll
            for (int r = 0; r < 4; r++) acc[i][j][r] = 0.f;

    // per-thread load slots: idx = tid + i*256, row = idx/4, seg = idx%4 (16B)
    auto loadChunk = [&](int g, int buf) {
        int p = g / NK;
        int kc = (g - p * NK) * 32;
        const __nv_bfloat16* Ab = Asrc[p] + kc;
        const __nv_bfloat16* Bb = Bsrc[p] + kc;
#pragma unroll
        for (int i = 0; i < 2; i++) {
            int idx = tid + i * 256;
            int row = idx >> 2, seg = idx & 3;
            uint32_t da = smem_u32(&sA[buf][row][seg * 8]);
            cpa16(da, Ab + (long)row * K + seg * 8, 16);
            int brow = n0 + row;
            int ok = brow < NN;
            uint32_t db = smem_u32(&sB[buf][row][seg * 8]);
            cpa16(db, Bb + (long)(ok ? brow : 0) * K + seg * 8, ok ? 16 : 0);
        }
    };

    loadChunk(0, 0);
    CPA_COMMIT();

    for (int g = 0; g < total; g++) {
        int buf = g & 1;
        if (g + 1 < total) {
            loadChunk(g + 1, buf ^ 1);
            CPA_COMMIT();
            CPA_WAIT(1);
        } else {
            CPA_WAIT(0);
        }
        __syncthreads();

#pragma unroll
        for (int ks = 0; ks < 2; ks++) {
            uint32_t a[4][4];
#pragma unroll
            for (int mi = 0; mi < 4; mi++) {
                // mat=lane/8: m_off=(mat&1)*8+row_in, k_off=(mat>>1)*8
                int mr = wm * 64 + mi * 16 + ((lane >> 3) & 1) * 8 + (lane & 7);
                int kk = ks * 16 + (lane >> 4) * 8;
                ldm_x4(a[mi], smem_u32(&sA[buf][mr][kk]));
            }
            uint32_t bf[2][4];
#pragma unroll
            for (int ni = 0; ni < 2; ni++) {
                // mat=lane/8: n_off=(mat>>1)*8+row_in, k_off=(mat&1)*8
                int nr = wn * 32 + ni * 16 + (lane >> 4) * 8 + (lane & 7);
                int kk = ks * 16 + ((lane >> 3) & 1) * 8;
                ldm_x4(bf[ni], smem_u32(&sB[buf][nr][kk]));
            }
#pragma unroll
            for (int mi = 0; mi < 4; mi++)
#pragma unroll
                for (int nj = 0; nj < 4; nj++)
                    mma16816(acc[mi][nj], a[mi],
                             bf[nj >> 1][(nj & 1) * 2], bf[nj >> 1][(nj & 1) * 2 + 1]);
        }
        __syncthreads();
    }

    // epilogue
    const int mbase = m0 + wm * 64;
    const int nbase = n0 + wn * 32;
    float* Cb = Cp + (long)b * sC;
    const float* rb = (EPI == 2) ? resid + (long)b * ((long)CC * NN) : nullptr;
#pragma unroll
    for (int mi = 0; mi < 4; mi++) {
        int mr0 = mbase + mi * 16 + (lane >> 2);
        int mr1 = mr0 + 8;
        float es0 = 1.f, eh0 = 0.f, es1 = 1.f, eh1 = 0.f;
        if (EPI == 1) { eh0 = g_bstk[mr0]; eh1 = g_bstk[mr1]; }
        if (EPI == 2) {
            es0 = g_escale[mr0]; eh0 = g_eshift[mr0];
            es1 = g_escale[mr1]; eh1 = g_eshift[mr1];
        }
#pragma unroll
        for (int nj = 0; nj < 4; nj++) {
            int n = nbase + nj * 8 + (lane & 3) * 2;
            if (n >= NN) continue;
            float2 v0 = make_float2(acc[mi][nj][0], acc[mi][nj][1]);
            float2 v1 = make_float2(acc[mi][nj][2], acc[mi][nj][3]);
            if (EPI == 2) {
                float2 r0 = *(const float2*)(rb + (long)mr0 * NN + n);
                float2 r1 = *(const float2*)(rb + (long)mr1 * NN + n);
                v0.x = v0.x * es0 + eh0 + r0.x; v0.y = v0.y * es0 + eh0 + r0.y;
                v1.x = v1.x * es1 + eh1 + r1.x; v1.y = v1.y * es1 + eh1 + r1.y;
            } else {
                v0.x += eh0; v0.y += eh0; v1.x += eh1; v1.y += eh1;
            }
            *(float2*)(Cb + (long)mr0 * NN + n) = v0;
            *(float2*)(Cb + (long)mr1 * NN + n) = v1;
        }
    }
}

// ---------------------------------------------------------------------------
// Launch
// ---------------------------------------------------------------------------
extern "C" void kernel_launch(void* const* d_in, const int* in_sizes, int n_in,
                              void* d_out, int out_size) {
    const float* x     = (const float*)d_in[0];
    const float* wt    = (const float*)d_in[1];
    const float* bt    = (const float*)d_in[2];
    const float* wp    = (const float*)d_in[3];
    const float* bp    = (const float*)d_in[4];
    const float* wg    = (const float*)d_in[5];
    const float* bg    = (const float*)d_in[6];
    const float* wW    = (const float*)d_in[7];
    const float* bW    = (const float*)d_in[8];
    const float* gamma = (const float*)d_in[9];
    const float* beta  = (const float*)d_in[10];
    const float* mean  = (const float*)d_in[11];
    const float* var   = (const float*)d_in[12];
    float* out = (float*)d_out;

    float *p_xj, *p_tpg, *p_phi, *p_gp, *p_attn, *p_y;
    __nv_bfloat16 *p_xhT, *p_xlT, *p_yhT, *p_ylT, *p_whi, *p_wlo, *p_wWhi, *p_wWlo;
    cudaGetSymbolAddress((void**)&p_xj, g_xj);
    cudaGetSymbolAddress((void**)&p_tpg, g_tpg);
    cudaGetSymbolAddress((void**)&p_phi, g_phi);
    cudaGetSymbolAddress((void**)&p_gp, g_gp);
    cudaGetSymbolAddress((void**)&p_attn, g_attn);
    cudaGetSymbolAddress((void**)&p_y, g_y);
    cudaGetSymbolAddress((void**)&p_xhT, g_xhT);
    cudaGetSymbolAddress((void**)&p_xlT, g_xlT);
    cudaGetSymbolAddress((void**)&p_yhT, g_yhT);
    cudaGetSymbolAddress((void**)&p_ylT, g_ylT);
    cudaGetSymbolAddress((void**)&p_whi, g_whi);
    cudaGetSymbolAddress((void**)&p_wlo, g_wlo);
    cudaGetSymbolAddress((void**)&p_wWhi, g_wWhi);
    cudaGetSymbolAddress((void**)&p_wWlo, g_wWlo);

    // 1. joint gather (fp32 residual copy)
    {
        long total = (long)BSZ * CC * NN;
        joint_kernel<<<(unsigned)((total + 255) / 256), 256>>>(x);
    }
    // 2. weight prep
    {
        long total = (long)CTPG * CC;
        wsplit_stack_kernel<<<(unsigned)((total + 255) / 256), 256>>>(wt, wp, wg, bt, bp, bg);
        wsplitW_kernel<<<(unsigned)(((long)CC * CI + 255) / 256), 256>>>(wW);
        bnprep_kernel<<<(CC + 255) / 256, 256>>>(gamma, beta, mean, var, bW);
    }
    // 3. xj -> xj^T hi/lo bf16
    {
        dim3 grid((NN + 31) / 32, CC / 32, BSZ);
        tsplit_kernel<<<grid, dim3(32, 8)>>>(p_xj, p_xhT, p_xlT, CC, NN);
    }
    // 4. stacked theta|phi|g conv (tensor mma): tpg[b] = Wstk * xj[b] + bstk
    {
        dim3 grid((NN + 127) / 128, CTPG / 128, BSZ);   // 7 x 18 x 32
        mma_gemm_kernel<1><<<grid, 256>>>(p_whi, p_wlo, p_xhT, p_xlT,
                                          p_tpg, CC, (long)CTPG * NN, nullptr);
    }
    // 5. 2x2 maxpool
    {
        int total = 2 * BSZ * CI * MM;
        pool_kernel<<<(total + 255) / 256, 256>>>();
    }
    // 6. f[b] = theta^T * phi   (SIMT fp32)
    {
        dim3 grid((MM + 63) / 64, (NN + 63) / 64, BSZ);
        gemm_kernel<true, false><<<grid, 256>>>(
            p_tpg, p_phi, p_attn, NN, MM, CI,
            (long)CTPG * NN, (long)CI * MM, (long)NN * MM);
    }
    // 7. softmax
    {
        int rows = BSZ * NN;
        softmax_kernel<<<(rows * 32 + 255) / 256, 256>>>();
    }
    // 8. y[b] = g[b] * attn[b]^T   (SIMT fp32)
    {
        dim3 grid((NN + 63) / 64, (CI + 63) / 64, BSZ);
        gemm_kernel<false, true><<<grid, 256>>>(
            p_gp, p_attn, p_y, CI, NN, MM,
            (long)CI * MM, (long)NN * MM, (long)CI * NN);
    }
    // 9. y -> y^T hi/lo bf16
    {
        dim3 grid((NN + 31) / 32, CI / 32, BSZ);
        tsplit_kernel<<<grid, dim3(32, 8)>>>(p_y, p_yhT, p_ylT, CI, NN);
    }
    // 10. W conv (tensor mma) + BN + residual -> out
    {
        dim3 grid((NN + 127) / 128, CC / 128, BSZ);     // 7 x 12 x 32
        mma_gemm_kernel<2><<<grid, 256>>>(p_wWhi, p_wWlo, p_yhT, p_ylT,
                                          out, CI, (long)CC * NN, p_xj);
    }
}